// round 11
// baseline (speedup 1.0000x reference)
#include <cuda_runtime.h>
#include <cuda_bf16.h>
#include <math.h>
#include <stdint.h>

// ---------------- problem constants ----------------
#define BATCH 64
#define SEQ   64
#define EMB   256
#define UNITS 512
#define GRU   256
#define FC    1024
#define VOCAB 50000

// ---------------- scratch (device globals; no allocation allowed) ----------------
__device__ float g_hidproj[BATCH * UNITS];
__device__ float g_scorep[4 * BATCH * SEQ];       // 4 column-partials of attention logits
__device__ float g_gx[BATCH * 2 * EMB];
__device__ float g_fcin[BATCH * (GRU + UNITS)];
__device__ float g_t1[BATCH * FC];
__device__ float g_t2[BATCH * FC];

// ---------------- packed dual-fp32 FMA (B300 FFMA2; baseline Blackwell PTX) ----------------
__device__ __forceinline__ uint64_t ffma2(uint64_t a, uint64_t b, uint64_t c) {
    uint64_t d;
    asm("fma.rn.f32x2 %0, %1, %2, %3;" : "=l"(d) : "l"(a), "l"(b), "l"(c));
    return d;
}
__device__ __forceinline__ uint64_t dup2(float x) {
    uint64_t d; uint32_t u = __float_as_uint(x);
    asm("mov.b64 %0, {%1, %1};" : "=l"(d) : "r"(u));
    return d;
}

// ================= gemm8: f32x2 SIMT GEMM, 8x8 thread tile =================
// C[M,N] = A[M,K] @ B[K,N] + bias.  CTA tile 64x128, 128 threads (4 warps).
// Thread tile 8(m) x 8(n). A staged duplicated (Asd[k][2m]=Asd[k][2m+1]) so the
// FFMA2 a-operand is a direct LDS pair; B pairs come from row-major Bs.
// Per kk per thread: 6 LDS.128 + 32 FFMA2  ->  fma-pipe bound (FFMA2 peak).
// Requires: M % 64 == 0, K % 32 == 0, N % 8 == 0.
#define G8_AROW 132
#define G8_ASZ  (32 * G8_AROW)           // floats per A buffer (4224)
#define G8_BSZ  (32 * 128)               // floats per B buffer (4096)
#define G8_SMEM ((2 * (G8_ASZ + G8_BSZ)) * 4)   // 66560 bytes

__global__ __launch_bounds__(128) void gemm8(
    const float* __restrict__ A, const float* __restrict__ B,
    const float* __restrict__ bias, float* __restrict__ C,
    int M, int N, int K)
{
    extern __shared__ float sm[];
    float* Asd = sm;                     // [2][32][G8_AROW]
    float* Bs  = sm + 2 * G8_ASZ;        // [2][32][128]

    const int tid = threadIdx.x;
    const int tx = tid & 15, ty = tid >> 4;
    const int n0 = blockIdx.x * 128, m0 = blockIdx.y * 64;
    const int NT = K >> 5;

    // A staging: 4 float4/thread; k4 = tid&7 fixed, m = (tid>>3)+16e
    const int ak4 = tid & 7, am0 = tid >> 3;
    // B staging: 8 float4/thread; f4 = tid&31 fixed, krow = (tid>>5)+4e
    const int bf4 = tid & 31, bk0 = tid >> 5;
    const bool bok = (n0 + bf4 * 4) < N;   // N%4==0 -> whole quad

    uint64_t acc[8][4];
#pragma unroll
    for (int i = 0; i < 8; i++)
#pragma unroll
        for (int j = 0; j < 4; j++) acc[i][j] = 0ull;

    float4 ar[4], br[8];
    // ---- prefetch + stage tile 0 ----
#pragma unroll
    for (int e = 0; e < 4; e++)
        ar[e] = *(const float4*)&A[(m0 + am0 + 16 * e) * K + ak4 * 4];
#pragma unroll
    for (int e = 0; e < 8; e++)
        br[e] = bok ? *(const float4*)&B[(bk0 + 4 * e) * N + n0 + bf4 * 4]
                    : make_float4(0.f, 0.f, 0.f, 0.f);
#pragma unroll
    for (int e = 0; e < 4; e++) {
        const float* v = (const float*)&ar[e];
        int m = am0 + 16 * e;
#pragma unroll
        for (int j = 0; j < 4; j++)
            *(float2*)&Asd[(ak4 * 4 + j) * G8_AROW + 2 * m] = make_float2(v[j], v[j]);
    }
#pragma unroll
    for (int e = 0; e < 8; e++)
        *(float4*)&Bs[(bk0 + 4 * e) * 128 + bf4 * 4] = br[e];
    __syncthreads();

    for (int s = 0; s < NT; s++) {
        const int b = s & 1;
        if (s + 1 < NT) {
            const int kb = (s + 1) << 5;
#pragma unroll
            for (int e = 0; e < 4; e++)
                ar[e] = *(const float4*)&A[(m0 + am0 + 16 * e) * K + kb + ak4 * 4];
#pragma unroll
            for (int e = 0; e < 8; e++)
                br[e] = bok ? *(const float4*)&B[(kb + bk0 + 4 * e) * N + n0 + bf4 * 4]
                            : make_float4(0.f, 0.f, 0.f, 0.f);
        }
        const float* Ab = Asd + b * G8_ASZ + ty * 16;
        const float* Bb = Bs  + b * G8_BSZ + tx * 8;
#pragma unroll 4
        for (int kk = 0; kk < 32; kk++) {
            ulonglong2 a01 = *(const ulonglong2*)(Ab + kk * G8_AROW);
            ulonglong2 a23 = *(const ulonglong2*)(Ab + kk * G8_AROW + 4);
            ulonglong2 a45 = *(const ulonglong2*)(Ab + kk * G8_AROW + 8);
            ulonglong2 a67 = *(const ulonglong2*)(Ab + kk * G8_AROW + 12);
            ulonglong2 b01 = *(const ulonglong2*)(Bb + kk * 128);
            ulonglong2 b23 = *(const ulonglong2*)(Bb + kk * 128 + 4);
            uint64_t aa[8] = {a01.x, a01.y, a23.x, a23.y, a45.x, a45.y, a67.x, a67.y};
            uint64_t bb[4] = {b01.x, b01.y, b23.x, b23.y};
#pragma unroll
            for (int i = 0; i < 8; i++) {
#pragma unroll
                for (int j = 0; j < 4; j++)
                    acc[i][j] = ffma2(aa[i], bb[j], acc[i][j]);
            }
        }
        if (s + 1 < NT) {
            const int nb = b ^ 1;
#pragma unroll
            for (int e = 0; e < 4; e++) {
                const float* v = (const float*)&ar[e];
                int m = am0 + 16 * e;
#pragma unroll
                for (int j = 0; j < 4; j++)
                    *(float2*)&Asd[nb * G8_ASZ + (ak4 * 4 + j) * G8_AROW + 2 * m] =
                        make_float2(v[j], v[j]);
            }
#pragma unroll
            for (int e = 0; e < 8; e++)
                *(float4*)&Bs[nb * G8_BSZ + (bk0 + 4 * e) * 128 + bf4 * 4] = br[e];
        }
        __syncthreads();
    }

    // ---- epilogue (N % 8 == 0 for all uses) ----
    const int bn = n0 + tx * 8;
    if (bn < N) {
        float4 bv0 = *(const float4*)&bias[bn];
        float4 bv1 = *(const float4*)&bias[bn + 4];
#pragma unroll
        for (int i = 0; i < 8; i++) {
            int m = m0 + ty * 8 + i;
            float2 p0 = *(float2*)&acc[i][0];
            float2 p1 = *(float2*)&acc[i][1];
            float2 p2 = *(float2*)&acc[i][2];
            float2 p3 = *(float2*)&acc[i][3];
            float4 o0 = make_float4(p0.x + bv0.x, p0.y + bv0.y, p1.x + bv0.z, p1.y + bv0.w);
            float4 o1 = make_float4(p2.x + bv1.x, p2.y + bv1.y, p3.x + bv1.z, p3.y + bv1.w);
            *(float4*)&C[m * N + bn] = o0;
            *(float4*)&C[m * N + bn + 4] = o1;
        }
    }
}

// ================= attn_score: fused (qs@W1 + b1 + hidproj) -> tanh -> dot V ========
// Same mainloop as gemm8 with M=4096, N=512, K=256 hardwired (no guards).
// Epilogue: per-row partial score over this CTA's 128 columns -> g_scorep[bx][row].
__global__ __launch_bounds__(128) void attn_score(
    const float* __restrict__ A,       // qs [4096, 256]
    const float* __restrict__ B,       // W1 [256, 512]
    const float* __restrict__ b1,
    const float* __restrict__ hidproj, // [64, 512]
    const float* __restrict__ V,       // [512]
    float* __restrict__ scorep)        // [4][4096]
{
    extern __shared__ float sm[];
    float* Asd = sm;
    float* Bs  = sm + 2 * G8_ASZ;

    const int tid = threadIdx.x;
    const int tx = tid & 15, ty = tid >> 4;
    const int n0 = blockIdx.x * 128, m0 = blockIdx.y * 64;
    const int K = 256, N = 512, NT = 8;

    const int ak4 = tid & 7, am0 = tid >> 3;
    const int bf4 = tid & 31, bk0 = tid >> 5;

    uint64_t acc[8][4];
#pragma unroll
    for (int i = 0; i < 8; i++)
#pragma unroll
        for (int j = 0; j < 4; j++) acc[i][j] = 0ull;

    float4 ar[4], br[8];
#pragma unroll
    for (int e = 0; e < 4; e++)
        ar[e] = *(const float4*)&A[(m0 + am0 + 16 * e) * K + ak4 * 4];
#pragma unroll
    for (int e = 0; e < 8; e++)
        br[e] = *(const float4*)&B[(bk0 + 4 * e) * N + n0 + bf4 * 4];
#pragma unroll
    for (int e = 0; e < 4; e++) {
        const float* v = (const float*)&ar[e];
        int m = am0 + 16 * e;
#pragma unroll
        for (int j = 0; j < 4; j++)
            *(float2*)&Asd[(ak4 * 4 + j) * G8_AROW + 2 * m] = make_float2(v[j], v[j]);
    }
#pragma unroll
    for (int e = 0; e < 8; e++)
        *(float4*)&Bs[(bk0 + 4 * e) * 128 + bf4 * 4] = br[e];
    __syncthreads();

    for (int s = 0; s < NT; s++) {
        const int b = s & 1;
        if (s + 1 < NT) {
            const int kb = (s + 1) << 5;
#pragma unroll
            for (int e = 0; e < 4; e++)
                ar[e] = *(const float4*)&A[(m0 + am0 + 16 * e) * K + kb + ak4 * 4];
#pragma unroll
            for (int e = 0; e < 8; e++)
                br[e] = *(const float4*)&B[(kb + bk0 + 4 * e) * N + n0 + bf4 * 4];
        }
        const float* Ab = Asd + b * G8_ASZ + ty * 16;
        const float* Bb = Bs  + b * G8_BSZ + tx * 8;
#pragma unroll 4
        for (int kk = 0; kk < 32; kk++) {
            ulonglong2 a01 = *(const ulonglong2*)(Ab + kk * G8_AROW);
            ulonglong2 a23 = *(const ulonglong2*)(Ab + kk * G8_AROW + 4);
            ulonglong2 a45 = *(const ulonglong2*)(Ab + kk * G8_AROW + 8);
            ulonglong2 a67 = *(const ulonglong2*)(Ab + kk * G8_AROW + 12);
            ulonglong2 b01 = *(const ulonglong2*)(Bb + kk * 128);
            ulonglong2 b23 = *(const ulonglong2*)(Bb + kk * 128 + 4);
            uint64_t aa[8] = {a01.x, a01.y, a23.x, a23.y, a45.x, a45.y, a67.x, a67.y};
            uint64_t bb[4] = {b01.x, b01.y, b23.x, b23.y};
#pragma unroll
            for (int i = 0; i < 8; i++) {
#pragma unroll
                for (int j = 0; j < 4; j++)
                    acc[i][j] = ffma2(aa[i], bb[j], acc[i][j]);
            }
        }
        if (s + 1 < NT) {
            const int nb = b ^ 1;
#pragma unroll
            for (int e = 0; e < 4; e++) {
                const float* v = (const float*)&ar[e];
                int m = am0 + 16 * e;
#pragma unroll
                for (int j = 0; j < 4; j++)
                    *(float2*)&Asd[nb * G8_ASZ + (ak4 * 4 + j) * G8_AROW + 2 * m] =
                        make_float2(v[j], v[j]);
            }
#pragma unroll
            for (int e = 0; e < 8; e++)
                *(float4*)&Bs[nb * G8_BSZ + (bk0 + 4 * e) * 128 + bf4 * 4] = br[e];
        }
        __syncthreads();
    }

    // ---- epilogue: score partial.  batch = blockIdx.y (64 aligned rows per CTA) ----
    const int bt = blockIdx.y;                    // batch index
    float hp[8], vv[8];
#pragma unroll
    for (int j = 0; j < 8; j++) {
        int col = n0 + tx * 8 + j;
        hp[j] = hidproj[bt * UNITS + col] + b1[col];
        vv[j] = V[col];
    }
#pragma unroll
    for (int i = 0; i < 8; i++) {
        float rsum = 0.f;
#pragma unroll
        for (int j = 0; j < 4; j++) {
            float2 p = *(float2*)&acc[i][j];
            rsum += tanhf(p.x + hp[2 * j]) * vv[2 * j];
            rsum += tanhf(p.y + hp[2 * j + 1]) * vv[2 * j + 1];
        }
#pragma unroll
        for (int o = 1; o < 16; o <<= 1)
            rsum += __shfl_xor_sync(0xffffffff, rsum, o);
        if (tx == 0)
            scorep[blockIdx.x * (BATCH * SEQ) + m0 + ty * 8 + i] = rsum;
    }
}

// ================= dense8_k: batch-tiled dense, 8 batches per block ================
// out[b, o] = in[b,:] . W[:,o] + bias[o] for b in [8*by, 8*by+8).
// Input tile lives in smem as ins[k][10] (pairs 8B-aligned, broadcast reads).
__global__ __launch_bounds__(256) void dense8_k(
    const float* __restrict__ in, const float* __restrict__ W,
    const float* __restrict__ bias, float* __restrict__ out,
    int IN, int OUT)
{
    extern __shared__ float ins[];               // [IN][10]
    const int o = blockIdx.x * 256 + threadIdx.x;
    const int bg = blockIdx.y * 8;
#pragma unroll
    for (int bb = 0; bb < 8; bb++)
        for (int k = threadIdx.x; k < IN; k += 256)
            ins[k * 10 + bb] = in[(bg + bb) * IN + k];
    __syncthreads();

    uint64_t acc[4] = {0ull, 0ull, 0ull, 0ull};
#pragma unroll 8
    for (int k = 0; k < IN; k++) {
        uint64_t ww = dup2(W[k * OUT + o]);
        const uint64_t* ip = (const uint64_t*)&ins[k * 10];
        acc[0] = ffma2(ww, ip[0], acc[0]);
        acc[1] = ffma2(ww, ip[1], acc[1]);
        acc[2] = ffma2(ww, ip[2], acc[2]);
        acc[3] = ffma2(ww, ip[3], acc[3]);
    }
    float bv = bias[o];
#pragma unroll
    for (int j = 0; j < 4; j++) {
        float2 p = *(float2*)&acc[j];
        out[(bg + 2 * j) * OUT + o] = p.x + bv;
        out[(bg + 2 * j + 1) * OUT + o] = p.y + bv;
    }
}

// ---------------- softmax + context + embedding (grid: 4 x B, 64 thr) ----------------
__global__ __launch_bounds__(64) void softctx_k(
    const float* __restrict__ scorep, const float* __restrict__ qs,
    const int* __restrict__ x, const float* __restrict__ E,
    const float* __restrict__ bV,
    float* __restrict__ weights_out, float* __restrict__ gx)
{
    int b = blockIdx.y, part = blockIdx.x, t = threadIdx.x;
    __shared__ float w[SEQ];
    {
        int bs = b * SEQ + t;
        w[t] = scorep[bs] + scorep[4096 + bs] + scorep[2 * 4096 + bs]
             + scorep[3 * 4096 + bs] + bV[0];
    }
    __syncthreads();
    if (t < 32) {
        float a0 = w[t], a1 = w[t + 32];
        float m = fmaxf(a0, a1);
#pragma unroll
        for (int o = 16; o; o >>= 1) m = fmaxf(m, __shfl_xor_sync(0xffffffff, m, o));
        float e0 = expf(a0 - m), e1 = expf(a1 - m);
        float s = e0 + e1;
#pragma unroll
        for (int o = 16; o; o >>= 1) s += __shfl_xor_sync(0xffffffff, s, o);
        float inv = 1.f / s;
        w[t] = e0 * inv; w[t + 32] = e1 * inv;
    }
    __syncthreads();
    if (part == 0) weights_out[b * SEQ + t] = w[t];
    int e = part * 64 + t;
    float c = 0.f;
#pragma unroll 8
    for (int s2 = 0; s2 < SEQ; s2++)
        c = fmaf(w[s2], qs[(b * SEQ + s2) * EMB + e], c);
    gx[b * 2 * EMB + EMB + e] = c;
    gx[b * 2 * EMB + e] = E[x[b] * EMB + e];
}

// ---------------- GRU step (h0 = 0) ----------------
__global__ __launch_bounds__(256) void gru_k(
    const float* __restrict__ gx, const float* __restrict__ Kg,
    const float* __restrict__ bg, const float* __restrict__ features,
    float* __restrict__ state_out, float* __restrict__ fc_in)
{
    int b = blockIdx.x, g = threadIdx.x;
    __shared__ float sh[2 * EMB];
    sh[g] = gx[b * 2 * EMB + g];
    sh[g + 256] = gx[b * 2 * EMB + 256 + g];
    __syncthreads();
    float mz = bg[g], mr = bg[GRU + g], mh = bg[2 * GRU + g];
#pragma unroll 4
    for (int k = 0; k < 2 * EMB; k++) {
        float a = sh[k];
        const float* kr = Kg + k * 3 * GRU;
        mz = fmaf(a, kr[g], mz);
        mr = fmaf(a, kr[GRU + g], mr);
        mh = fmaf(a, kr[2 * GRU + g], mh);
    }
    const float* bgh = bg + 3 * GRU;
    float z = 1.f / (1.f + expf(-(mz + bgh[g])));
    float r = 1.f / (1.f + expf(-(mr + bgh[GRU + g])));
    float hc = tanhf(mh + r * bgh[2 * GRU + g]);
    float st = (1.f - z) * hc;
    state_out[b * GRU + g] = st;
    fc_in[b * (GRU + UNITS) + g] = st;
    fc_in[b * (GRU + UNITS) + GRU + g] = features[b * UNITS + g];
    fc_in[b * (GRU + UNITS) + GRU + 256 + g] = features[b * UNITS + 256 + g];
}

// ---------------- launch ----------------
extern "C" void kernel_launch(void* const* d_in, const int* in_sizes, int n_in,
                              void* d_out, int out_size)
{
    const int*   x        = (const int*)  d_in[0];
    const float* qs       = (const float*)d_in[1];
    const float* features = (const float*)d_in[2];
    const float* hidden   = (const float*)d_in[3];
    const float* E        = (const float*)d_in[4];
    const float* W1       = (const float*)d_in[5];
    const float* b1       = (const float*)d_in[6];
    const float* W2       = (const float*)d_in[7];
    const float* b2       = (const float*)d_in[8];
    const float* V        = (const float*)d_in[9];
    const float* bV       = (const float*)d_in[10];
    const float* Kg       = (const float*)d_in[11];
    /* d_in[12] = Ug dead (h0 == 0) */
    const float* bg       = (const float*)d_in[13];
    const float* Wf1      = (const float*)d_in[14];
    const float* bf1      = (const float*)d_in[15];
    const float* Wf2      = (const float*)d_in[16];
    const float* bf2      = (const float*)d_in[17];
    const float* Wo       = (const float*)d_in[18];
    const float* bo       = (const float*)d_in[19];

    float* out = (float*)d_out;
    float* logits      = out;
    float* state_out   = out + BATCH * VOCAB;
    float* weights_out = state_out + BATCH * GRU;

    float *hidproj, *scorep, *gx, *fcin, *t1, *t2;
    cudaGetSymbolAddress((void**)&hidproj, g_hidproj);
    cudaGetSymbolAddress((void**)&scorep,  g_scorep);
    cudaGetSymbolAddress((void**)&gx,      g_gx);
    cudaGetSymbolAddress((void**)&fcin,    g_fcin);
    cudaGetSymbolAddress((void**)&t1,      g_t1);
    cudaGetSymbolAddress((void**)&t2,      g_t2);

    cudaFuncSetAttribute(gemm8, cudaFuncAttributeMaxDynamicSharedMemorySize, G8_SMEM);
    cudaFuncSetAttribute(attn_score, cudaFuncAttributeMaxDynamicSharedMemorySize, G8_SMEM);

    // hidden @ W2 + b2  (batch-tiled dense: W2 read once per 8 batches)
    dense8_k<<<dim3(UNITS / 256, BATCH / 8), 256, UNITS * 10 * 4>>>(
        hidden, W2, b2, hidproj, UNITS, UNITS);
    // fused qs@W1 + b1 + hidproj -> tanh -> dot V  => 4 column-partial scores
    attn_score<<<dim3(4, BATCH), 128, G8_SMEM>>>(qs, W1, b1, hidproj, V, scorep);
    // softmax + context + embedding gather
    softctx_k<<<dim3(4, BATCH), 64>>>(scorep, qs, x, E, bV, weights_out, gx);
    // GRU (h0 = 0)
    gru_k<<<BATCH, 256>>>(gx, Kg, bg, features, state_out, fcin);
    // dense stack (batch-tiled)
    dense8_k<<<dim3(FC / 256, BATCH / 8), 256, (GRU + UNITS) * 10 * 4>>>(
        fcin, Wf1, bf1, t1, GRU + UNITS, FC);
    dense8_k<<<dim3(FC / 256, BATCH / 8), 256, FC * 10 * 4>>>(
        t1, Wf2, bf2, t2, FC, FC);
    // logits: M=64, N=50000, K=1024 — FFMA2 8x8 tile, 391 CTAs
    gemm8<<<dim3((VOCAB + 127) / 128, 1), 128, G8_SMEM>>>(
        t2, Wo, bo, logits, BATCH, VOCAB, FC);
}

// round 12
// speedup vs baseline: 1.2647x; 1.2647x over previous
#include <cuda_runtime.h>
#include <cuda_bf16.h>
#include <math.h>
#include <stdint.h>

// ---------------- problem constants ----------------
#define BATCH 64
#define SEQ   64
#define EMB   256
#define UNITS 512
#define GRU   256
#define FC    1024
#define VOCAB 50000

// ---------------- scratch (device globals; no allocation allowed) ----------------
__device__ float g_hidproj[BATCH * UNITS];
__device__ float g_qp[BATCH * SEQ * UNITS];       // qs@W1 + b1
__device__ float g_score[BATCH * SEQ];
__device__ float g_gx[BATCH * 2 * EMB];
__device__ float g_fcin[BATCH * (GRU + UNITS)];
__device__ float g_t1[BATCH * FC];
__device__ float g_t2[BATCH * FC];
__device__ float g_part[4 * BATCH * FC];          // K-split partials (max 4 x 64 x 1024)

// ---------------- packed dual-fp32 FMA (B300 FFMA2) ----------------
__device__ __forceinline__ uint64_t ffma2(uint64_t a, uint64_t b, uint64_t c) {
    uint64_t d;
    asm("fma.rn.f32x2 %0, %1, %2, %3;" : "=l"(d) : "l"(a), "l"(b), "l"(c));
    return d;
}
__device__ __forceinline__ uint64_t dup2(float x) {
    uint64_t d; uint32_t u = __float_as_uint(x);
    asm("mov.b64 %0, {%1, %1};" : "=l"(d) : "r"(u));
    return d;
}

// ================= f32x2 SIMT GEMM (round-10, known good) =================
// C[M,N] = A[M,K] @ B[K,N] + bias.  CTA 64x128, 256 threads, 8m x 4n tile.
#define GF_ROW 130
#define GF_ASZ (32 * GF_ROW)
#define GF_BSZ (32 * 128)
#define GF_SMEM ((2 * GF_ASZ + 2 * GF_BSZ) * 4)   // 66048 bytes

__global__ __launch_bounds__(256) void gemm_f32x2(
    const float* __restrict__ A, const float* __restrict__ B,
    const float* __restrict__ bias, float* __restrict__ C,
    int M, int N, int K)
{
    extern __shared__ float sm[];
    float* Asd = sm;
    float* Bs  = sm + 2 * GF_ASZ;

    const int tid = threadIdx.x, tx = tid & 31, ty = tid >> 5;
    const int n0 = blockIdx.x * 128, m0 = blockIdx.y * 64;
    const int NT = K >> 5;

    uint64_t acc[8][2];
#pragma unroll
    for (int i = 0; i < 8; i++) { acc[i][0] = 0ull; acc[i][1] = 0ull; }

    const int bn = n0 + tx * 4;
    const bool bok = bn < N;
    const int bkr = tid >> 5;

    float ar[8]; float4 br[4];
#pragma unroll
    for (int e = 0; e < 8; e++) {
        int idx = tid + e * 256;
        ar[e] = A[(m0 + (idx >> 5)) * K + (idx & 31)];
    }
#pragma unroll
    for (int e = 0; e < 4; e++)
        br[e] = bok ? *(const float4*)&B[(bkr + e * 8) * N + bn]
                    : make_float4(0.f, 0.f, 0.f, 0.f);
#pragma unroll
    for (int e = 0; e < 8; e++) {
        int idx = tid + e * 256;
        *(float2*)&Asd[(idx & 31) * GF_ROW + 2 * (idx >> 5)] = make_float2(ar[e], ar[e]);
    }
#pragma unroll
    for (int e = 0; e < 4; e++)
        *(float4*)&Bs[(bkr + e * 8) * 128 + tx * 4] = br[e];
    __syncthreads();

    for (int s = 0; s < NT; s++) {
        const int b = s & 1;
        if (s + 1 < NT) {
            const int kb = (s + 1) << 5;
#pragma unroll
            for (int e = 0; e < 8; e++) {
                int idx = tid + e * 256;
                ar[e] = A[(m0 + (idx >> 5)) * K + kb + (idx & 31)];
            }
#pragma unroll
            for (int e = 0; e < 4; e++)
                br[e] = bok ? *(const float4*)&B[(kb + bkr + e * 8) * N + bn]
                            : make_float4(0.f, 0.f, 0.f, 0.f);
        }
        const float* Ab = Asd + b * GF_ASZ + 2 * ty;
        const float* Bb = Bs  + b * GF_BSZ + tx * 4;
#pragma unroll 8
        for (int kk = 0; kk < 32; kk++) {
            uint64_t bb0 = *(const uint64_t*)(Bb + kk * 128);
            uint64_t bb1 = *(const uint64_t*)(Bb + kk * 128 + 2);
            const float* arow = Ab + kk * GF_ROW;
#pragma unroll
            for (int i = 0; i < 8; i++) {
                uint64_t aa = *(const uint64_t*)(arow + 16 * i);
                acc[i][0] = ffma2(aa, bb0, acc[i][0]);
                acc[i][1] = ffma2(aa, bb1, acc[i][1]);
            }
        }
        if (s + 1 < NT) {
            const int nb = b ^ 1;
#pragma unroll
            for (int e = 0; e < 8; e++) {
                int idx = tid + e * 256;
                *(float2*)&Asd[nb * GF_ASZ + (idx & 31) * GF_ROW + 2 * (idx >> 5)] =
                    make_float2(ar[e], ar[e]);
            }
#pragma unroll
            for (int e = 0; e < 4; e++)
                *(float4*)&Bs[nb * GF_BSZ + (bkr + e * 8) * 128 + tx * 4] = br[e];
        }
        __syncthreads();
    }

    if (bok) {
        float4 bv = *(const float4*)&bias[bn];
#pragma unroll
        for (int i = 0; i < 8; i++) {
            int m = m0 + ty + 8 * i;
            float2 p0 = *(float2*)&acc[i][0];
            float2 p1 = *(float2*)&acc[i][1];
            float4 o = make_float4(p0.x + bv.x, p0.y + bv.y, p1.x + bv.z, p1.y + bv.w);
            *(float4*)&C[m * N + bn] = o;
        }
    }
}

// ================= dense8_ks: batch-tiled (8) + K-split dense partials ==========
// part[c, b, o] = sum_{k in chunk c} in[b,k] * W[k,o]
// grid: (OUT/256, BATCH/8, KS).  smem: ins[KC][10] (8 batches, 8B-aligned pairs).
__global__ __launch_bounds__(256) void dense8_ks(
    const float* __restrict__ in, const float* __restrict__ W,
    float* __restrict__ part, int IN, int OUT, int KC)
{
    extern __shared__ float ins[];
    const int o = blockIdx.x * 256 + threadIdx.x;
    const int bg = blockIdx.y * 8;
    const int kbase = blockIdx.z * KC;

#pragma unroll
    for (int bb = 0; bb < 8; bb++)
        for (int k = threadIdx.x; k < KC; k += 256)
            ins[k * 10 + bb] = in[(bg + bb) * IN + kbase + k];
    __syncthreads();

    uint64_t acc[4] = {0ull, 0ull, 0ull, 0ull};
    const float* Wp = W + (size_t)kbase * OUT + o;
#pragma unroll 8
    for (int k = 0; k < KC; k++) {
        uint64_t ww = dup2(Wp[(size_t)k * OUT]);
        const uint64_t* ip = (const uint64_t*)&ins[k * 10];
        acc[0] = ffma2(ww, ip[0], acc[0]);
        acc[1] = ffma2(ww, ip[1], acc[1]);
        acc[2] = ffma2(ww, ip[2], acc[2]);
        acc[3] = ffma2(ww, ip[3], acc[3]);
    }
    float* pp = part + ((size_t)blockIdx.z * BATCH + bg) * OUT + o;
#pragma unroll
    for (int j = 0; j < 4; j++) {
        float2 p = *(float2*)&acc[j];
        pp[(2 * j) * OUT] = p.x;
        pp[(2 * j + 1) * OUT] = p.y;
    }
}

// ---------------- finisher: out[b,o] = sum_c part[c,b,o] + bias[o] ----------------
__global__ __launch_bounds__(256) void fin_k(
    const float* __restrict__ part, const float* __restrict__ bias,
    float* __restrict__ out, int OUT, int KS)
{
    int i = blockIdx.x * 256 + threadIdx.x;     // over BATCH*OUT
    float s = bias[i % OUT];
    for (int c = 0; c < KS; c++) s += part[c * BATCH * OUT + i];
    out[i] = s;
}

// ---------------- GRU finisher (h0 = 0): gates from partials ----------------
__global__ __launch_bounds__(256) void gru_fin(
    const float* __restrict__ part,      // [4][64][768]
    const float* __restrict__ bg,        // [2][768]
    const float* __restrict__ features,  // [64, 512]
    float* __restrict__ state_out, float* __restrict__ fc_in)
{
    const int b = blockIdx.x, g = threadIdx.x;
    float mz = 0.f, mr = 0.f, mh = 0.f;
#pragma unroll
    for (int c = 0; c < 4; c++) {
        const float* p = part + (c * BATCH + b) * (3 * GRU);
        mz += p[g]; mr += p[GRU + g]; mh += p[2 * GRU + g];
    }
    mz += bg[g]; mr += bg[GRU + g]; mh += bg[2 * GRU + g];
    const float* bgh = bg + 3 * GRU;
    float z = 1.f / (1.f + expf(-(mz + bgh[g])));
    float r = 1.f / (1.f + expf(-(mr + bgh[GRU + g])));
    float hc = tanhf(mh + r * bgh[2 * GRU + g]);
    float st = (1.f - z) * hc;
    state_out[b * GRU + g] = st;
    fc_in[b * (GRU + UNITS) + g] = st;
    fc_in[b * (GRU + UNITS) + GRU + g] = features[b * UNITS + g];
    fc_in[b * (GRU + UNITS) + GRU + 256 + g] = features[b * UNITS + 256 + g];
}

// ---------------- attention score ----------------
__global__ __launch_bounds__(256) void score_k(
    const float* __restrict__ qp, const float* __restrict__ hidproj,
    const float* __restrict__ V, const float* __restrict__ bV,
    float* __restrict__ score)
{
    int bs = blockIdx.x, b = bs >> 6, t = threadIdx.x;
    const float* qrow = qp + bs * UNITS;
    const float* hp = hidproj + b * UNITS;
    float s = 0.f;
    for (int u = t; u < UNITS; u += 256)
        s += tanhf(qrow[u] + hp[u]) * V[u];
    __shared__ float red[256];
    red[t] = s; __syncthreads();
    for (int o = 128; o > 0; o >>= 1) {
        if (t < o) red[t] += red[t + o];
        __syncthreads();
    }
    if (t == 0) score[bs] = red[0] + bV[0];
}

// ---------------- softmax + context + embedding (grid: 4 x B, 64 thr) ----------------
__global__ __launch_bounds__(64) void softctx_k(
    const float* __restrict__ score, const float* __restrict__ qs,
    const int* __restrict__ x, const float* __restrict__ E,
    float* __restrict__ weights_out, float* __restrict__ gx)
{
    int b = blockIdx.y, part = blockIdx.x, t = threadIdx.x;
    __shared__ float w[SEQ];
    w[t] = score[b * SEQ + t];
    __syncthreads();
    if (t < 32) {
        float a0 = w[t], a1 = w[t + 32];
        float m = fmaxf(a0, a1);
#pragma unroll
        for (int o = 16; o; o >>= 1) m = fmaxf(m, __shfl_xor_sync(0xffffffff, m, o));
        float e0 = expf(a0 - m), e1 = expf(a1 - m);
        float s = e0 + e1;
#pragma unroll
        for (int o = 16; o; o >>= 1) s += __shfl_xor_sync(0xffffffff, s, o);
        float inv = 1.f / s;
        w[t] = e0 * inv; w[t + 32] = e1 * inv;
    }
    __syncthreads();
    if (part == 0) weights_out[b * SEQ + t] = w[t];
    int e = part * 64 + t;
    float c = 0.f;
#pragma unroll 8
    for (int s2 = 0; s2 < SEQ; s2++)
        c = fmaf(w[s2], qs[(b * SEQ + s2) * EMB + e], c);
    gx[b * 2 * EMB + EMB + e] = c;
    gx[b * 2 * EMB + e] = E[x[b] * EMB + e];
}

// ---------------- launch ----------------
extern "C" void kernel_launch(void* const* d_in, const int* in_sizes, int n_in,
                              void* d_out, int out_size)
{
    const int*   x        = (const int*)  d_in[0];
    const float* qs       = (const float*)d_in[1];
    const float* features = (const float*)d_in[2];
    const float* hidden   = (const float*)d_in[3];
    const float* E        = (const float*)d_in[4];
    const float* W1       = (const float*)d_in[5];
    const float* b1       = (const float*)d_in[6];
    const float* W2       = (const float*)d_in[7];
    const float* b2       = (const float*)d_in[8];
    const float* V        = (const float*)d_in[9];
    const float* bV       = (const float*)d_in[10];
    const float* Kg       = (const float*)d_in[11];
    /* d_in[12] = Ug dead (h0 == 0) */
    const float* bg       = (const float*)d_in[13];
    const float* Wf1      = (const float*)d_in[14];
    const float* bf1      = (const float*)d_in[15];
    const float* Wf2      = (const float*)d_in[16];
    const float* bf2      = (const float*)d_in[17];
    const float* Wo       = (const float*)d_in[18];
    const float* bo       = (const float*)d_in[19];

    float* out = (float*)d_out;
    float* logits      = out;
    float* state_out   = out + BATCH * VOCAB;
    float* weights_out = state_out + BATCH * GRU;

    float *hidproj, *qp, *score, *gx, *fcin, *t1, *t2, *part;
    cudaGetSymbolAddress((void**)&hidproj, g_hidproj);
    cudaGetSymbolAddress((void**)&qp,      g_qp);
    cudaGetSymbolAddress((void**)&score,   g_score);
    cudaGetSymbolAddress((void**)&gx,      g_gx);
    cudaGetSymbolAddress((void**)&fcin,    g_fcin);
    cudaGetSymbolAddress((void**)&t1,      g_t1);
    cudaGetSymbolAddress((void**)&t2,      g_t2);
    cudaGetSymbolAddress((void**)&part,    g_part);

    cudaFuncSetAttribute(gemm_f32x2, cudaFuncAttributeMaxDynamicSharedMemorySize, GF_SMEM);

    // hidden @ W2 + b2  (batch-tile 8, K-split 4 -> 64 blocks)
    dense8_ks<<<dim3(UNITS / 256, BATCH / 8, 4), 256, 128 * 10 * 4>>>(
        hidden, W2, part, UNITS, UNITS, 128);
    fin_k<<<BATCH * UNITS / 256, 256>>>(part, b2, hidproj, UNITS, 4);
    // qs @ W1 + b1 : M=4096, N=512, K=256 (256 CTAs)
    gemm_f32x2<<<dim3(UNITS / 128, (BATCH * SEQ) / 64), 256, GF_SMEM>>>(
        qs, W1, b1, qp, BATCH * SEQ, UNITS, EMB);
    score_k<<<BATCH * SEQ, 256>>>(qp, hidproj, V, bV, score);
    softctx_k<<<dim3(4, BATCH), 64>>>(score, qs, x, E, weights_out, gx);
    // GRU matmul gx @ Kg (96 blocks) + gate finisher
    dense8_ks<<<dim3(3 * GRU / 256, BATCH / 8, 4), 256, 128 * 10 * 4>>>(
        gx, Kg, part, 2 * EMB, 3 * GRU, 128);
    gru_fin<<<BATCH, GRU>>>(part, bg, features, state_out, fcin);
    // fc1: [64,768] @ [768,1024]
    dense8_ks<<<dim3(FC / 256, BATCH / 8, 4), 256, 192 * 10 * 4>>>(
        fcin, Wf1, part, GRU + UNITS, FC, 192);
    fin_k<<<BATCH * FC / 256, 256>>>(part, bf1, t1, FC, 4);
    // fc2: [64,1024] @ [1024,1024]
    dense8_ks<<<dim3(FC / 256, BATCH / 8, 4), 256, 256 * 10 * 4>>>(
        t1, Wf2, part, FC, FC, 256);
    fin_k<<<BATCH * FC / 256, 256>>>(part, bf2, t2, FC, 4);
    // logits: M=64, N=50000, K=1024 — FFMA2 path, 391 CTAs
    gemm_f32x2<<<dim3((VOCAB + 127) / 128, 1), 256, GF_SMEM>>>(
        t2, Wo, bo, logits, BATCH, VOCAB, FC);
}